// round 5
// baseline (speedup 1.0000x reference)
#include <cuda_runtime.h>

#define NN 1024
#define EE 2048
#define CIN 4
#define HID 192
#define KCH 5
#define NL 4
#define NAUG 1152          // 5*HID (edge basis) + HID (root)
#define SA_STRIDE 132
#define SRAW_STRIDE 196
#define SMEM_GEMM ((192*SA_STRIDE + 128*SRAW_STRIDE)*4)   // 101376 + 100352 = 201728
#define SMEM_CHEB ((1024 + 16384 + 4096)*4)               // 86016

typedef unsigned long long ull;

// ---------------- device scratch (allocation-free) ----------------
__device__ float g_S[4*NN*CIN];       // S_k = lap(T_{k-1}), k=1..4
__device__ float g_h0[NN*HID];
__device__ float g_h1[NN*HID];
__device__ float g_Y[NN*NAUG];
__device__ float g_B[NL][HID*NAUG];   // B[i][j*1152 + k*192 + o]

// ---------------- f32x2 helpers ----------------
__device__ __forceinline__ void fma2(ull &c, ull a, ull b) {
    asm("fma.rn.f32x2 %0, %1, %2, %0;" : "+l"(c) : "l"(a), "l"(b));
}
__device__ __forceinline__ float2 up2(ull a) {
    float2 f; asm("mov.b64 {%0, %1}, %2;" : "=f"(f.x), "=f"(f.y) : "l"(a)); return f;
}

// ---------------- k_M: Mstack (36x4 blocks) + cheb prep (block 36,0) ----------------
__global__ void __launch_bounds__(256) k_M(const float* __restrict__ nn2_w,
                                           const float* __restrict__ nn2_b,
                                           const float* __restrict__ eenc_w,
                                           const float* __restrict__ eenc_b,
                                           const float* __restrict__ nn1_w,
                                           const float* __restrict__ nn1_b,
                                           const float* __restrict__ root_w,
                                           const int* __restrict__ ei,
                                           const float* __restrict__ x) {
    int t = threadIdx.x;
    if (blockIdx.x == 36) {
        if (blockIdx.y != 0) return;
        // ---- Cheb prep: deg, dinv, 4 scatter rounds, all in smem ----
        extern __shared__ float dsm[];
        float* sdeg = dsm;                 // [1024]
        float* sS   = dsm + 1024;          // [4][1024][4]
        float* sX   = dsm + 1024 + 16384;  // [1024][4]
        #pragma unroll
        for (int i = 0; i < 4; i++) sdeg[t + 256*i] = 0.f;
        #pragma unroll
        for (int i = 0; i < 64; i++) sS[t + 256*i] = 0.f;
        #pragma unroll
        for (int i = 0; i < 16; i++) sX[t + 256*i] = x[t + 256*i];
        __syncthreads();
        int s[8], d[8]; float w[8];
        #pragma unroll
        for (int j = 0; j < 8; j++) {
            int e = t*8 + j;
            s[j] = ei[e]; d[j] = ei[EE + e];
            atomicAdd(&sdeg[s[j]], 1.f);
        }
        __syncthreads();
        float dv[4];
        #pragma unroll
        for (int i = 0; i < 4; i++) dv[i] = sdeg[t + 256*i];
        __syncthreads();
        #pragma unroll
        for (int i = 0; i < 4; i++) sdeg[t + 256*i] = dv[i] > 0.f ? rsqrtf(dv[i]) : 0.f;
        __syncthreads();
        #pragma unroll
        for (int j = 0; j < 8; j++) w[j] = -sdeg[s[j]] * sdeg[d[j]];
        // round 1: S0 += w * x[src]
        #pragma unroll
        for (int j = 0; j < 8; j++)
            #pragma unroll
            for (int c = 0; c < 4; c++)
                atomicAdd(&sS[d[j]*4 + c], w[j] * sX[s[j]*4 + c]);
        __syncthreads();
        // round 2: S1 += w * S0[src]
        #pragma unroll
        for (int j = 0; j < 8; j++)
            #pragma unroll
            for (int c = 0; c < 4; c++)
                atomicAdd(&sS[4096 + d[j]*4 + c], w[j] * sS[s[j]*4 + c]);
        __syncthreads();
        // round 3: S2 += w * (2*S1[src] - x[src])
        #pragma unroll
        for (int j = 0; j < 8; j++)
            #pragma unroll
            for (int c = 0; c < 4; c++)
                atomicAdd(&sS[8192 + d[j]*4 + c],
                          w[j] * (2.f*sS[4096 + s[j]*4 + c] - sX[s[j]*4 + c]));
        __syncthreads();
        // round 4: S3 += w * (2*S2[src] - S0[src])
        #pragma unroll
        for (int j = 0; j < 8; j++)
            #pragma unroll
            for (int c = 0; c < 4; c++)
                atomicAdd(&sS[12288 + d[j]*4 + c],
                          w[j] * (2.f*sS[8192 + s[j]*4 + c] - sS[s[j]*4 + c]));
        __syncthreads();
        #pragma unroll
        for (int i = 0; i < 64; i++) g_S[t + 256*i] = sS[t + 256*i];
        return;
    }

    // ---- Mstack blocks ----
    int i = blockIdx.y;
    __shared__ float2 sG[5*HID];
    if (t < HID) {
        float acc[5] = {0.f, 0.f, 0.f, 0.f, 0.f};
        const float* W = nn1_w + i*HID*HID;
        for (int j0 = 0; j0 < HID; j0++) {
            float w = W[j0*HID + t];
            acc[0] += eenc_w[j0]*w;
            acc[1] += eenc_w[HID + j0]*w;
            acc[2] += eenc_w[2*HID + j0]*w;
            acc[3] += eenc_w[3*HID + j0]*w;
            acc[4] += eenc_b[j0]*w;
        }
        acc[4] += nn1_b[i*HID + t];
        #pragma unroll
        for (int k = 0; k < 5; k++) sG[k*HID + t] = make_float2(acc[k], acc[k]);
    }
    // root copy into g_B cols 960..1151
    {
        int m = blockIdx.x*1024 + t*4;
        int j = m / HID, o = m - j*HID;
        float4 v = *(const float4*)(root_w + (size_t)i*HID*HID + m);
        *(float4*)(g_B[i] + j*NAUG + 5*HID + o) = v;
    }
    __syncthreads();

    int m4 = (blockIdx.x*256 + t) * 4;
    const float* W = nn2_w + (size_t)i * HID * (HID*HID);
    ull acc[5][2] = {};
    #pragma unroll 4
    for (int j = 0; j < HID; j++) {
        float4 v = __ldg((const float4*)(W + (size_t)j*(HID*HID) + m4));
        ull v01, v23;
        asm("mov.b64 %0, {%1, %2};" : "=l"(v01) : "f"(v.x), "f"(v.y));
        asm("mov.b64 %0, {%1, %2};" : "=l"(v23) : "f"(v.z), "f"(v.w));
        #pragma unroll
        for (int k = 0; k < 5; k++) {
            ull gk = *(const ull*)&sG[k*HID + j];
            fma2(acc[k][0], gk, v01);
            fma2(acc[k][1], gk, v23);
        }
    }
    float4 b = __ldg((const float4*)(nn2_b + (size_t)i*(HID*HID) + m4));
    float2 a40 = up2(acc[4][0]), a41 = up2(acc[4][1]);
    a40.x += b.x; a40.y += b.y; a41.x += b.z; a41.y += b.w;
    int j2 = m4 / HID;
    int o  = m4 - j2 * HID;
    float* dst = g_B[i] + j2*NAUG + o;
    #pragma unroll
    for (int k = 0; k < 4; k++) {
        *(float2*)(dst + k*HID)     = up2(acc[k][0]);
        *(float2*)(dst + k*HID + 2) = up2(acc[k][1]);
    }
    *(float2*)(dst + 4*HID)     = a40;
    *(float2*)(dst + 4*HID + 2) = a41;
}

// ---------------- Cheb output: h0 = sum_k T_k @ W_k + b ----------------
__global__ void k_cheb_out(const float* __restrict__ x,
                           const float* __restrict__ cw, const float* __restrict__ cb) {
    int n = blockIdx.x, o = threadIdx.x;   // 1024 x 192
    __shared__ float tx[KCH][CIN];
    if (o < CIN) {
        float xv = x[n*CIN + o];
        float s1 = g_S[n*4+o], s2 = g_S[4096 + n*4+o];
        float s3 = g_S[2*4096 + n*4+o], s4 = g_S[3*4096 + n*4+o];
        tx[0][o] = xv;
        tx[1][o] = s1;
        tx[2][o] = 2.f*s2 - xv;
        tx[3][o] = 2.f*s3 - s1;
        tx[4][o] = 2.f*s4 - 2.f*s2 + xv;
    }
    __syncthreads();
    float acc = cb[o];
    #pragma unroll
    for (int k = 0; k < KCH; k++)
        #pragma unroll
        for (int c = 0; c < CIN; c++)
            acc += tx[k][c] * cw[(k*CIN + c)*HID + o];
    g_h0[n*HID + o] = acc;
}

// ---------------- fused LN + node GEMM (issue-lean, M-packed f32x2) ----------------
// Y[1024,1152] = LN(h_in) @ B ; root cols -> hout (+resid +cb)
__global__ void __launch_bounds__(256)
k_gemm(int layer, const float* __restrict__ lng, const float* __restrict__ lnb,
       const float* __restrict__ cb) {
    extern __shared__ float sm2[];
    float* sA = sm2;                    // [192][132] transposed, LN'd A
    float* sW = sm2 + 192*SA_STRIDE;    // phase1: raw A [128][196]; phase2: B-dup [192][128w]
    __shared__ float smu[128], srs[128];
    const float* hin  = (layer & 1) ? g_h1 : g_h0;
    float*       hout = (layer & 1) ? g_h0 : g_h1;
    const float* Bm = g_B[layer];
    int t = threadIdx.x;
    int m0 = blockIdx.x * 128;
    int n0 = blockIdx.y * 64;
    int do_ln = (layer > 0);

    // phase 1: raw A tile load (coalesced float4)
    {
        const float4* h4 = (const float4*)(hin + (size_t)m0*HID);
        #pragma unroll
        for (int i = 0; i < 24; i++) {
            int q = t + i*256;
            int m = q / 48, c4 = q - m*48;
            float4 v = h4[m*48 + c4];
            *(float4*)&sW[m*SRAW_STRIDE + c4*4] = v;
        }
    }
    __syncthreads();
    // phase 1b: per-row LN stats (thread per row, two-pass)
    if (do_ln) {
        if (t < 128) {
            const float* row = &sW[t*SRAW_STRIDE];
            float s = 0.f;
            #pragma unroll 8
            for (int k = 0; k < 192; k++) s += row[k];
            float mu = s * (1.f/192.f);
            float q2 = 0.f;
            #pragma unroll 8
            for (int k = 0; k < 192; k++) { float dd = row[k] - mu; q2 = fmaf(dd, dd, q2); }
            smu[t] = mu;
            srs[t] = rsqrtf(q2*(1.f/192.f) + 1e-5f);
        }
        __syncthreads();
    }
    // phase 1c: normalize + ReLU + transpose into sA[k][m]
    {
        int m = t & 127, kh = t >> 7;
        float mu = 0.f, rs = 0.f;
        if (do_ln) { mu = smu[m]; rs = srs[m]; }
        const float* row = &sW[m*SRAW_STRIDE];
        int k0 = kh*96;
        for (int k = k0; k < k0 + 96; k++) {
            float v = row[k];
            if (do_ln) v = fmaxf(0.f, (v - mu)*rs*__ldg(lng + k) + __ldg(lnb + k));
            sA[k*SA_STRIDE + m] = v;
        }
    }
    __syncthreads();
    // phase 2: B tile, stored duplicated (b,b) pairs, word stride 128 per kk
    {
        #pragma unroll
        for (int i = 0; i < 24; i++) {
            int q = t + i*256;
            int kk = q >> 5, ch = q & 31;
            float2 v = __ldg((const float2*)(Bm + kk*NAUG + n0 + ch*2));
            *(float4*)&sW[kk*128 + ch*4] = make_float4(v.x, v.x, v.y, v.y);
        }
    }
    __syncthreads();

    // phase 3: 20-instr inner loop (4 LDS.128 + 16 FMA2)
    int tx = t & 15, ty = t >> 4;
    const float* aB = sA + ty*8;
    const float* bB = sW + tx*8;
    ull acc[4][4] = {};
    #pragma unroll 4
    for (int kk = 0; kk < 192; kk++) {
        ulonglong2 a01 = *(const ulonglong2*)(aB + kk*SA_STRIDE);
        ulonglong2 a23 = *(const ulonglong2*)(aB + kk*SA_STRIDE + 4);
        ulonglong2 b01 = *(const ulonglong2*)(bB + kk*128);
        ulonglong2 b23 = *(const ulonglong2*)(bB + kk*128 + 4);
        fma2(acc[0][0], a01.x, b01.x); fma2(acc[0][1], a01.x, b01.y);
        fma2(acc[0][2], a01.x, b23.x); fma2(acc[0][3], a01.x, b23.y);
        fma2(acc[1][0], a01.y, b01.x); fma2(acc[1][1], a01.y, b01.y);
        fma2(acc[1][2], a01.y, b23.x); fma2(acc[1][3], a01.y, b23.y);
        fma2(acc[2][0], a23.x, b01.x); fma2(acc[2][1], a23.x, b01.y);
        fma2(acc[2][2], a23.x, b23.x); fma2(acc[2][3], a23.x, b23.y);
        fma2(acc[3][0], a23.y, b01.x); fma2(acc[3][1], a23.y, b01.y);
        fma2(acc[3][2], a23.y, b23.x); fma2(acc[3][3], a23.y, b23.y);
    }

    // epilogue
    if (n0 < 5*HID) {
        #pragma unroll
        for (int pm = 0; pm < 4; pm++) {
            int m = m0 + ty*8 + pm*2;
            float2 c0 = up2(acc[pm][0]), c1 = up2(acc[pm][1]);
            float2 c2 = up2(acc[pm][2]), c3 = up2(acc[pm][3]);
            *(float4*)(g_Y + (size_t)m*NAUG + n0 + tx*4)       = make_float4(c0.x, c1.x, c2.x, c3.x);
            *(float4*)(g_Y + (size_t)(m+1)*NAUG + n0 + tx*4)   = make_float4(c0.y, c1.y, c2.y, c3.y);
        }
    } else {
        int ob = n0 - 5*HID + tx*4;
        float4 cv = *(const float4*)(cb + ob);
        #pragma unroll
        for (int pm = 0; pm < 4; pm++) {
            int m = m0 + ty*8 + pm*2;
            float2 c0 = up2(acc[pm][0]), c1 = up2(acc[pm][1]);
            float2 c2 = up2(acc[pm][2]), c3 = up2(acc[pm][3]);
            float4 r0 = make_float4(c0.x + cv.x, c1.x + cv.y, c2.x + cv.z, c3.x + cv.w);
            float4 r1 = make_float4(c0.y + cv.x, c1.y + cv.y, c2.y + cv.z, c3.y + cv.w);
            if (do_ln) {  // residual (layers 1..3)
                float4 h0v = *(const float4*)(hin + (size_t)m*HID + ob);
                float4 h1v = *(const float4*)(hin + (size_t)(m+1)*HID + ob);
                r0.x += h0v.x; r0.y += h0v.y; r0.z += h0v.z; r0.w += h0v.w;
                r1.x += h1v.x; r1.y += h1v.y; r1.z += h1v.z; r1.w += h1v.w;
            }
            *(float4*)(hout + (size_t)m*HID + ob)     = r0;
            *(float4*)(hout + (size_t)(m+1)*HID + ob) = r1;
        }
    }
}

// ---------------- per-edge combine + scatter ----------------
__global__ void k_escatter(int layer, const int* __restrict__ ei, const float* __restrict__ attr) {
    float* hout = (layer & 1) ? g_h0 : g_h1;
    int e = blockIdx.x;            // 2048 blocks
    int o = threadIdx.x;           // 192
    int s = ei[e], d = ei[EE + e];
    float4 a = __ldg((const float4*)(attr + e*4));
    const float* Ys = g_Y + (size_t)s*NAUG;
    float v = Ys[4*HID + o]
            + a.x*Ys[o] + a.y*Ys[HID + o] + a.z*Ys[2*HID + o] + a.w*Ys[3*HID + o];
    atomicAdd(&hout[d*HID + o], v);
}

// ---------------- fused final LN + head ----------------
__global__ void k_out(const float* __restrict__ lng, const float* __restrict__ lnb,
                      const float* __restrict__ ow, const float* __restrict__ ob,
                      float* __restrict__ out) {
    int n = blockIdx.x, t = threadIdx.x;    // 1024 x 192
    __shared__ float red[6];
    __shared__ float r0s[6], r1s[6];
    int warp = t >> 5, lane = t & 31;
    float v = g_h0[n*HID + t];
    float s = v;
    #pragma unroll
    for (int o = 16; o > 0; o >>= 1) s += __shfl_xor_sync(0xffffffffu, s, o);
    if (lane == 0) red[warp] = s;
    __syncthreads();
    float tot = 0.f;
    #pragma unroll
    for (int w = 0; w < 6; w++) tot += red[w];
    float mu = tot * (1.f/192.f);
    float d = v - mu;
    float s2 = d * d;
    #pragma unroll
    for (int o = 16; o > 0; o >>= 1) s2 += __shfl_xor_sync(0xffffffffu, s2, o);
    __syncthreads();
    if (lane == 0) red[warp] = s2;
    __syncthreads();
    float var = 0.f;
    #pragma unroll
    for (int w = 0; w < 6; w++) var += red[w];
    var *= (1.f/192.f);
    float z = fmaxf(0.f, d * rsqrtf(var + 1e-5f) * lng[t] + lnb[t]);
    float p0 = z * ow[t*2];
    float p1 = z * ow[t*2 + 1];
    #pragma unroll
    for (int o = 16; o > 0; o >>= 1) {
        p0 += __shfl_xor_sync(0xffffffffu, p0, o);
        p1 += __shfl_xor_sync(0xffffffffu, p1, o);
    }
    if (lane == 0) { r0s[warp] = p0; r1s[warp] = p1; }
    __syncthreads();
    if (t == 0) {
        float a0 = ob[0], a1 = ob[1];
        #pragma unroll
        for (int w = 0; w < 6; w++) { a0 += r0s[w]; a1 += r1s[w]; }
        out[n*2]     = a0;
        out[n*2 + 1] = a1;
    }
}

// ---------------- launcher ----------------
extern "C" void kernel_launch(void* const* d_in, const int* in_sizes, int n_in,
                              void* d_out, int out_size) {
    const float* x       = (const float*)d_in[0];
    const int*   ei      = (const int*)  d_in[1];
    const float* attr    = (const float*)d_in[2];
    const float* cheb_w  = (const float*)d_in[4];
    const float* cheb_b  = (const float*)d_in[5];
    const float* eenc_w  = (const float*)d_in[6];
    const float* eenc_b  = (const float*)d_in[7];
    const float* nn1_w   = (const float*)d_in[8];
    const float* nn1_b   = (const float*)d_in[9];
    const float* nn2_w   = (const float*)d_in[10];
    const float* nn2_b   = (const float*)d_in[11];
    const float* root_w  = (const float*)d_in[12];
    const float* conv_b  = (const float*)d_in[13];
    const float* ln_g    = (const float*)d_in[14];
    const float* ln_b    = (const float*)d_in[15];
    const float* out_w   = (const float*)d_in[16];
    const float* out_b   = (const float*)d_in[17];
    float* out = (float*)d_out;

    cudaFuncSetAttribute(k_gemm, cudaFuncAttributeMaxDynamicSharedMemorySize, SMEM_GEMM);
    cudaFuncSetAttribute(k_M,    cudaFuncAttributeMaxDynamicSharedMemorySize, SMEM_CHEB);

    // Mstack + cheb prep (cheb block hides under the HBM stream)
    k_M<<<dim3(37, NL), 256, SMEM_CHEB>>>(nn2_w, nn2_b, eenc_w, eenc_b,
                                          nn1_w, nn1_b, root_w, ei, x);
    k_cheb_out<<<NN, HID>>>(x, cheb_w, cheb_b);

    // 4 NNConv layers
    for (int i = 0; i < NL; i++) {
        k_gemm<<<dim3(8, 18), 256, SMEM_GEMM>>>(i, ln_g + i*HID, ln_b + i*HID,
                                                conv_b + i*HID);
        k_escatter<<<EE, HID>>>(i, ei, attr);
    }

    // fused final LN + head
    k_out<<<NN, HID>>>(ln_g, ln_b, out_w, out_b, out);
}